// round 11
// baseline (speedup 1.0000x reference)
#include <cuda_runtime.h>

#define T_STEPS 730
#define N_GRID  8000
#define NZ      1e-5f

__constant__ float c_LO[18] = {-3.f, 0.f, 0.f, 0.f, 0.f, 0.f, 0.f, 0.f, 0.005f, 1.f, 0.f, 1.f, 0.f, 1.f, 0.f, 0.f, 0.f, 0.f};
__constant__ float c_HI[18] = { 5.f,20.f, 1.f, 1.f, 5.f,50.f, 1.f, 1.f, 0.995f, 2000.f, 20.f, 300.f, 1.f, 5.f, 1.f, 1.f, 1.f, 1.f};

__device__ __forceinline__ float fast_ex2(float a) {
    float r;
    asm("ex2.approx.f32 %0, %1;" : "=f"(r) : "f"(a));
    return r;
}

// Block: 64 threads = 2 warps, 32 cells. Warp 0 = upper chain (snow..smav),
// warp 1 = lower chain (res, gw), pipelined one step apart via SMEM.
__global__ __launch_bounds__(64) void prms_kernel(
    const float* __restrict__ x,      // [T_STEPS, N_GRID, 3]
    const float* __restrict__ params, // [T_STEPS, N_GRID, 18]
    float* __restrict__ out)          // [T_STEPS, N_GRID]
{
    const int lane = threadIdx.x & 31;
    const int wid  = threadIdx.x >> 5;
    const int g    = blockIdx.x * 32 + lane;      // 250 blocks * 32 = 8000 exact

    __shared__ float s_sas[2][32];
    __shared__ float s_sro[2][32];
    __shared__ float s_excs[2][32];

    // ---- per-cell parameters from the LAST timestep slice (both warps; prologue) ----
    const float* pp = params + ((size_t)(T_STEPS - 1) * N_GRID + g) * 18;
    float pr[18];
#pragma unroll
    for (int i = 0; i < 18; i++) {
        float s = 1.0f / (1.0f + expf(-pp[i]));
        pr[i] = c_LO[i] + s * (c_HI[i] - c_LO[i]);
    }
    const float tt     = pr[0],  ddf   = pr[1],  alpha = pr[2],  beta  = pr[3];
    const float stor   = pr[4],  retip = pr[5],  fscn  = pr[6],  scx   = pr[7];
    const float flz    = pr[8],  stot  = pr[9],  cgw   = pr[10], resmax= pr[11];
    const float k1     = pr[12], k2    = pr[13], k3    = pr[14], k4    = pr[15];
    const float k5     = pr[16], k6    = pr[17];

    const float scn        = fscn * scx;
    const float remx       = (1.0f - flz) * stot;
    const float smax       = flz * stot;
    const float inv_remx   = 1.0f / remx;
    const float inv_smax   = 1.0f / smax;
    const float inv_resmax = 1.0f / resmax;
    const float one_m_beta = 1.0f - beta;
    const float one_m_alpha= 1.0f - alpha;
    const float c2         = (scx - scn) * inv_remx;
    const float lg2k1      = log2f(k1);

    // ---- upper state (warp 0) ----
    float snow = 0.001f, xin = 0.001f, rstor = 0.001f, rechr = 0.001f, smav = 0.001f;
    // ---- lower state (warp 1) ----
    float res = 0.001f, gw = 0.001f;

    // =================== upper(t) — identical math to R10 ===================
    auto upper = [&](float P, float Tc, float Ep, int slot) {
        // ---- snow ----
        const float flux_ps  = (Tc <= tt) ? P : 0.0f;
        const float flux_pr  = P - flux_ps;
        const float snow1    = snow + flux_ps;
        const float mpot     = fmaxf(ddf * (Tc - tt), 0.0f);
        const float flux_m   = fminf(mpot, snow1);
        snow = fmaxf(snow1 - mpot, NZ);

        // ---- interception ----
        const float flux_pim = flux_pr * one_m_beta;
        const float flux_psm = flux_pr * beta;
        const float flux_pby = flux_psm * one_m_alpha;
        const float flux_pin = flux_psm * alpha;
        const float xin1 = xin + flux_pin;
        const float flux_ptf = fmaxf(xin1 - stor, 0.0f);
        const float xin2 = fminf(xin1, stor);
        const float epb  = Ep * beta;
        const float flux_ein = fminf(epb, xin2);
        xin = fmaxf(xin2 - epb, NZ);

        // ---- impervious storage ----
        const float rs1 = rstor + fmaf(flux_m, one_m_beta, flux_pim);
        const float flux_sas = fmaxf(rs1 - retip, 0.0f);
        const float rs2 = fminf(rs1, retip);
        const float eib = one_m_beta * Ep;
        const float flux_eim = fminf(eib, rs2);
        rstor = fmaxf(rs2 - eib, NZ);

        // ---- surface runoff / recharge ----
        const float sro_lin = fminf(fmaxf(fmaf(c2, rechr, scn), 0.0f), 1.0f);
        const float inflow  = fmaf(flux_m, beta, flux_ptf) + flux_pby;
        const float flux_sro = sro_lin * inflow;
        const float flux_inf = inflow - flux_sro;
        const float re1 = rechr + flux_inf;
        const float flux_pc = fmaxf(re1 - remx, 0.0f);
        const float re2 = fminf(re1, remx);
        const float ep_net = Ep - flux_ein - flux_eim;
        const float evap_max_a = re2 * inv_remx * ep_net;
        const float flux_ea = fminf(evap_max_a, re2);
        rechr = fmaxf(re2 - flux_ea, NZ);

        // ---- soil moisture ----
        const float sm1 = smav + flux_pc;
        const float flux_excs = fmaxf(sm1 - smax, 0.0f);
        const float sm2 = fminf(sm1, smax);
        float transp = (rechr < ep_net)
                         ? fminf(fmaxf(sm2 * inv_smax * (ep_net - flux_ea), 0.0f), sm2)
                         : 0.0f;
        smav = fmaxf(sm2 - transp, NZ);

        s_sas[slot][lane]  = flux_sas;
        s_sro[slot][lane]  = flux_sro;
        s_excs[slot][lane] = flux_excs;
    };

    // =================== lower(t) — identical math to R10 ===================
    auto lower = [&](float flux_sas, float flux_sro, float flux_excs) -> float {
        const float flux_sep  = fminf(cgw, flux_excs);
        const float flux_qres = flux_excs - flux_sep;
        res += flux_qres;
        const float ratio = res * inv_resmax;
        float flux_gad = fast_ex2(fmaf(k2, __log2f(ratio), lg2k1));  // k1*ratio^k2
        flux_gad = fminf(flux_gad, res);
        res = fmaxf(res - flux_gad, NZ);
        float flux_ras = fminf(fmaf(k4 * res, res, k3 * res), res);
        res = fmaxf(res - flux_ras, NZ);

        gw += flux_gad + flux_sep;
        const float flux_bas = k5 * gw;
        gw = fmaxf(gw - flux_bas, NZ);
        const float flux_snk = k6 * gw;
        gw = fmaxf(gw - flux_snk, NZ);

        return flux_sas + flux_sro + flux_bas + flux_ras;
    };

    // ---- per-warp walkers ----
    float Pb[2], Tb[2], Eb[2];
    const float* xp = nullptr;
    float*       op = out + g;                      // out[t-1] walker (warp 1)

    if (wid == 0) {
        // forcing double-buffer + full t=0 iteration (R9-validated indexing)
        const float* x0 = x + (size_t)g * 3;
        Pb[0] = x0[0]; Tb[0] = x0[1]; Eb[0] = x0[2];
        const float* x1 = x + ((size_t)N_GRID + g) * 3;
        Pb[1] = x1[0]; Tb[1] = x1[1]; Eb[1] = x1[2];
        xp = x + ((size_t)2 * N_GRID + g) * 3;

        const float P = Pb[0], Tc = Tb[0], Ep = Eb[0];
        Pb[0] = xp[0]; Tb[0] = xp[1]; Eb[0] = xp[2];   // x[2] -> slot 0
        xp += (size_t)N_GRID * 3;
        upper(P, Tc, Ep, 0);                            // writes smem slot 0
    }
    __syncthreads();                                    // slot 0 visible to warp 1

    // ---- pipelined main loop: warp0 upper(t) || warp1 lower(t-1) ----
#pragma unroll 2
    for (int t = 1; t < T_STEPS; t++) {
        const int b = t & 1;
        if (wid == 0) {
            const float P  = Pb[b];
            const float Tc = Tb[b];
            const float Ep = Eb[b];
            if (t + 2 < T_STEPS) {                      // prefetch x[t+2]
                Pb[b] = xp[0]; Tb[b] = xp[1]; Eb[b] = xp[2];
            }
            xp += (size_t)N_GRID * 3;
            upper(P, Tc, Ep, b);                        // writes slot b
        } else {
            const int pb = b ^ 1;                       // slot (t-1)&1
            const float q = lower(s_sas[pb][lane], s_sro[pb][lane], s_excs[pb][lane]);
            *op = q;                                    // out[t-1]
            op += N_GRID;
        }
        __syncthreads();                                // hand off slot b to next iter
    }

    // ---- epilogue: lower(T-1) reads slot (T-1)&1 = 1 ----
    if (wid == 1) {
        const int pb = (T_STEPS - 1) & 1;
        *op = lower(s_sas[pb][lane], s_sro[pb][lane], s_excs[pb][lane]);
    }
}

extern "C" void kernel_launch(void* const* d_in, const int* in_sizes, int n_in,
                              void* d_out, int out_size) {
    // Identify inputs by element count (robust to ordering):
    //   x:          730*8000*3  = 17,520,000
    //   parameters: 730*8000*18 = 105,120,000
    const float* x = nullptr;
    const float* params = nullptr;
    for (int i = 0; i < n_in; i++) {
        if (in_sizes[i] == T_STEPS * N_GRID * 3)  x = (const float*)d_in[i];
        if (in_sizes[i] == T_STEPS * N_GRID * 18) params = (const float*)d_in[i];
    }
    float* out = (float*)d_out;

    const int blocks = N_GRID / 32;   // 250 blocks, 2 warps each (upper + lower)
    prms_kernel<<<blocks, 64>>>(x, params, out);
}

// round 12
// speedup vs baseline: 1.0737x; 1.0737x over previous
#include <cuda_runtime.h>

#define T_STEPS 730
#define N_GRID  8000
#define NZ      1e-5f

__constant__ float c_LO[18] = {-3.f, 0.f, 0.f, 0.f, 0.f, 0.f, 0.f, 0.f, 0.005f, 1.f, 0.f, 1.f, 0.f, 1.f, 0.f, 0.f, 0.f, 0.f};
__constant__ float c_HI[18] = { 5.f,20.f, 1.f, 1.f, 5.f,50.f, 1.f, 1.f, 0.995f, 2000.f, 20.f, 300.f, 1.f, 5.f, 1.f, 1.f, 1.f, 1.f};

__device__ __forceinline__ float fast_ex2(float a) {
    float r;
    asm("ex2.approx.f32 %0, %1;" : "=f"(r) : "f"(a));
    return r;
}

__global__ __launch_bounds__(64) void prms_kernel(
    const float* __restrict__ x,      // [T_STEPS, N_GRID, 3]
    const float* __restrict__ params, // [T_STEPS, N_GRID, 18]
    float* __restrict__ out)          // [T_STEPS, N_GRID]
{
    const int g = blockIdx.x * blockDim.x + threadIdx.x;
    if (g >= N_GRID) return;

    // ---- per-cell parameters from the LAST timestep slice ----
    const float* pp = params + ((size_t)(T_STEPS - 1) * N_GRID + g) * 18;
    float pr[18];
#pragma unroll
    for (int i = 0; i < 18; i++) {
        float s = 1.0f / (1.0f + expf(-pp[i]));
        pr[i] = c_LO[i] + s * (c_HI[i] - c_LO[i]);
    }
    const float tt     = pr[0],  ddf   = pr[1],  alpha = pr[2],  beta  = pr[3];
    const float stor   = pr[4],  retip = pr[5],  fscn  = pr[6],  scx   = pr[7];
    const float flz    = pr[8],  stot  = pr[9],  cgw   = pr[10], resmax= pr[11];
    const float k1     = pr[12], k2    = pr[13], k3    = pr[14], k4    = pr[15];
    const float k5     = pr[16], k6    = pr[17];

    const float scn        = fscn * scx;
    const float remx       = (1.0f - flz) * stot;
    const float smax       = flz * stot;
    const float inv_remx   = 1.0f / remx;
    const float inv_smax   = 1.0f / smax;
    const float inv_resmax = 1.0f / resmax;
    const float one_m_beta = 1.0f - beta;
    const float one_m_alpha= 1.0f - alpha;
    const float c2         = (scx - scn) * inv_remx;
    const float lg2k1      = log2f(k1);

    // ---- states by stage ----
    float snow = 0.001f, xin = 0.001f, rstor = 0.001f;   // stage A
    float rechr = 0.001f, smav = 0.001f;                 // stage B
    float res = 0.001f, gw = 0.001f;                     // stage C

    // ======== stage A(t): snow / interception / impervious ========
    auto stageA = [&](float P, float Tc, float Ep,
                      float& inflow_o, float& epnet_o, float& sas_o) {
        const float flux_ps  = (Tc <= tt) ? P : 0.0f;
        const float flux_pr  = P - flux_ps;
        const float snow1    = snow + flux_ps;
        const float mpot     = fmaxf(ddf * (Tc - tt), 0.0f);
        const float flux_m   = fminf(mpot, snow1);
        snow = fmaxf(snow1 - mpot, NZ);

        const float flux_pim = flux_pr * one_m_beta;
        const float flux_psm = flux_pr * beta;
        const float flux_pby = flux_psm * one_m_alpha;
        const float flux_pin = flux_psm * alpha;
        const float xin1 = xin + flux_pin;
        const float flux_ptf = fmaxf(xin1 - stor, 0.0f);
        const float xin2 = fminf(xin1, stor);
        const float epb  = Ep * beta;
        const float flux_ein = fminf(epb, xin2);
        xin = fmaxf(xin2 - epb, NZ);

        const float rs1 = rstor + fmaf(flux_m, one_m_beta, flux_pim);
        const float flux_sas = fmaxf(rs1 - retip, 0.0f);
        const float rs2 = fminf(rs1, retip);
        const float eib = one_m_beta * Ep;
        const float flux_eim = fminf(eib, rs2);
        rstor = fmaxf(rs2 - eib, NZ);

        inflow_o = fmaf(flux_m, beta, flux_ptf) + flux_pby;
        epnet_o  = Ep - flux_ein - flux_eim;
        sas_o    = flux_sas;
    };

    // ======== stage B(t): recharge / soil moisture ========
    auto stageB = [&](float inflow, float ep_net,
                      float& sro_o, float& excs_o) {
        const float sro_lin = fminf(fmaxf(fmaf(c2, rechr, scn), 0.0f), 1.0f);
        const float flux_sro = sro_lin * inflow;
        const float flux_inf = inflow - flux_sro;
        const float re1 = rechr + flux_inf;
        const float flux_pc = fmaxf(re1 - remx, 0.0f);
        const float re2 = fminf(re1, remx);
        const float evap_max_a = re2 * inv_remx * ep_net;
        const float flux_ea = fminf(evap_max_a, re2);
        rechr = fmaxf(re2 - flux_ea, NZ);

        const float sm1 = smav + flux_pc;
        const float flux_excs = fmaxf(sm1 - smax, 0.0f);
        const float sm2 = fminf(sm1, smax);
        float transp = (rechr < ep_net)
                         ? fminf(fmaxf(sm2 * inv_smax * (ep_net - flux_ea), 0.0f), sm2)
                         : 0.0f;
        smav = fmaxf(sm2 - transp, NZ);

        sro_o = flux_sro; excs_o = flux_excs;
    };

    // ======== stage C(t): reservoir / groundwater ========
    auto stageC = [&](float flux_sas, float flux_sro, float flux_excs) -> float {
        const float flux_sep  = fminf(cgw, flux_excs);
        const float flux_qres = flux_excs - flux_sep;
        res += flux_qres;
        const float ratio = res * inv_resmax;
        float flux_gad = fast_ex2(fmaf(k2, __log2f(ratio), lg2k1));
        flux_gad = fminf(flux_gad, res);
        res = fmaxf(res - flux_gad, NZ);
        float flux_ras = fminf(fmaf(k4 * res, res, k3 * res), res);
        res = fmaxf(res - flux_ras, NZ);

        gw += flux_gad + flux_sep;
        const float flux_bas = k5 * gw;
        gw = fmaxf(gw - flux_bas, NZ);
        const float flux_snk = k6 * gw;
        gw = fmaxf(gw - flux_snk, NZ);

        return flux_sas + flux_sro + flux_bas + flux_ras;
    };

    // ---- forcing double-buffer (R7/R10-validated indexing) ----
    float Pb[2], Tb[2], Eb[2];
    {
        const float* x0 = x + (size_t)g * 3;
        Pb[0] = x0[0]; Tb[0] = x0[1]; Eb[0] = x0[2];
        const float* x1 = x + ((size_t)N_GRID + g) * 3;
        Pb[1] = x1[0]; Tb[1] = x1[1]; Eb[1] = x1[2];
    }
    const float* xp = x + ((size_t)2 * N_GRID + g) * 3;
    float*       op = out + g;

    // ---- pipeline carries ----
    float inflow_c, epnet_c;        // A(t-1) -> B at iter t
    float sas1, sas2;               // sas(t-1), sas(t-2)
    float sro_c, excs_c;            // B(t-2) outputs for C at iter t

    // ---- prologue: t=0 ----
    {
        const float P = Pb[0], Tc = Tb[0], Ep = Eb[0];
        Pb[0] = xp[0]; Tb[0] = xp[1]; Eb[0] = xp[2];      // x[2] -> slot 0
        xp += (size_t)N_GRID * 3;
        stageA(P, Tc, Ep, inflow_c, epnet_c, sas2);       // A(0); sas2 = sas(0)
    }
    // ---- prologue: t=1 ----
    {
        const float P = Pb[1], Tc = Tb[1], Ep = Eb[1];
        Pb[1] = xp[0]; Tb[1] = xp[1]; Eb[1] = xp[2];      // x[3] -> slot 1
        xp += (size_t)N_GRID * 3;
        stageB(inflow_c, epnet_c, sro_c, excs_c);         // B(0)
        stageA(P, Tc, Ep, inflow_c, epnet_c, sas1);       // A(1); sas1 = sas(1)
    }

    // ---- main loop: t = 2..T-1 :  C(t-2) | B(t-1) | A(t) ----
#pragma unroll 2
    for (int t = 2; t < T_STEPS; t++) {
        const int b = t & 1;
        const float P  = Pb[b];
        const float Tc = Tb[b];
        const float Ep = Eb[b];
        if (t + 2 < T_STEPS) {                 // prefetch x[t+2] into slot b
            Pb[b] = xp[0]; Tb[b] = xp[1]; Eb[b] = xp[2];
        }
        xp += (size_t)N_GRID * 3;

        // C for step t-2 (independent chain 1)
        const float q = stageC(sas2, sro_c, excs_c);

        // B for step t-1 (independent chain 2) — consumes carries, then they refill
        float sro_n, excs_n;
        stageB(inflow_c, epnet_c, sro_n, excs_n);

        // A for step t (independent chain 3)
        float inflow_n, epnet_n, sas_n;
        stageA(P, Tc, Ep, inflow_n, epnet_n, sas_n);

        *op = q;                               // out[t-2]
        op += N_GRID;

        // shift carries
        sas2 = sas1; sas1 = sas_n;
        inflow_c = inflow_n; epnet_c = epnet_n;
        sro_c = sro_n; excs_c = excs_n;
    }

    // ---- epilogue ----
    {
        // C(T-2)
        *op = stageC(sas2, sro_c, excs_c);
        op += N_GRID;
        // B(T-1) then C(T-1)
        float sro_n, excs_n;
        stageB(inflow_c, epnet_c, sro_n, excs_n);
        *op = stageC(sas1, sro_n, excs_n);
    }
}

extern "C" void kernel_launch(void* const* d_in, const int* in_sizes, int n_in,
                              void* d_out, int out_size) {
    // Identify inputs by element count (robust to ordering):
    //   x:          730*8000*3  = 17,520,000
    //   parameters: 730*8000*18 = 105,120,000
    const float* x = nullptr;
    const float* params = nullptr;
    for (int i = 0; i < n_in; i++) {
        if (in_sizes[i] == T_STEPS * N_GRID * 3)  x = (const float*)d_in[i];
        if (in_sizes[i] == T_STEPS * N_GRID * 18) params = (const float*)d_in[i];
    }
    float* out = (float*)d_out;

    const int threads = 64;
    const int blocks = (N_GRID + threads - 1) / threads;  // 125 blocks
    prms_kernel<<<blocks, threads>>>(x, params, out);
}